// round 7
// baseline (speedup 1.0000x reference)
#include <cuda_runtime.h>
#include <cstdint>
#include <math.h>

// Depthwise conv1d, K=7, 'same' padding, softmax over taps — single fused kernel.
// x: (B, C, T) fp32; weight: (H, 1, 7); head for channel c is c % H (H=16).
// One block = one full T=4096 row. Tile loaded via cp.async.cg (LDGSTS):
// MLP=4 per thread with ZERO destination registers -> full occupancy (R3 fix).

#define KSIZE 7
#define T_LEN 4096
#define THREADS 256
#define Q (T_LEN / 4)          // 1024 elems between a thread's 4 chunks
#define SHIFT 4                // s[SHIFT + i] = x[i]; zeros at s[1..3]

__device__ __forceinline__ void cp_async16(unsigned int saddr, const void* gptr) {
    asm volatile("cp.async.cg.shared.global [%0], [%1], 16;"
                 :: "r"(saddr), "l"(gptr));
}

__global__ __launch_bounds__(THREADS, 8)
void lconv1d_cpasync_kernel(const float* __restrict__ x,
                            const float* __restrict__ wraw,
                            float* __restrict__ out) {
    __shared__ float s[SHIFT + T_LEN + 3];
    __shared__ float sw[KSIZE];

    const int row = blockIdx.x;               // b*C + c
    const size_t base = (size_t)row * T_LEN;
    const int tid = threadIdx.x;
    const int p = tid * 4;

    const unsigned int s_u32 = (unsigned int)__cvta_generic_to_shared(s);

    // 4 in-flight bulk copies per thread, no destination registers.
    #pragma unroll
    for (int i = 0; i < 4; i++) {
        const int q = p + i * Q;
        cp_async16(s_u32 + (SHIFT + q) * 4, x + base + q);
    }
    asm volatile("cp.async.commit_group;");

    // Zero padding at both row ends ('same' padding, PAD=3).
    if (tid < 3) {
        s[1 + tid] = 0.f;
        s[SHIFT + T_LEN + tid] = 0.f;
    }

    // Fused softmax over this row's head taps (threads 0..6); hides under cp.async.
    if (tid < KSIZE) {
        const int h = row & 15;               // C=1024 multiple of H=16
        float v[KSIZE];
        float m = -1e30f;
        #pragma unroll
        for (int k = 0; k < KSIZE; k++) {
            v[k] = __ldg(&wraw[h * KSIZE + k]);
            m = fmaxf(m, v[k]);
        }
        float sum = 0.f;
        #pragma unroll
        for (int k = 0; k < KSIZE; k++) sum += __expf(v[k] - m);
        sw[tid] = __expf(v[tid] - m) / sum;
    }

    asm volatile("cp.async.wait_group 0;");
    __syncthreads();

    const float w0 = sw[0], w1 = sw[1], w2 = sw[2], w3 = sw[3],
                w4 = sw[4], w5 = sw[5], w6 = sw[6];

    // 4 chunks; window for outputs [q..q+3] is s[q .. q+11] (SHIFT=4 folds the -4).
    #pragma unroll
    for (int i = 0; i < 4; i++) {
        const int q = p + i * Q;
        const float4 a = *reinterpret_cast<const float4*>(&s[q]);
        const float4 b = *reinterpret_cast<const float4*>(&s[q + 4]);
        const float4 c = *reinterpret_cast<const float4*>(&s[q + 8]);
        float4 r;
        r.x = w0*a.y + w1*a.z + w2*a.w + w3*b.x + w4*b.y + w5*b.z + w6*b.w;
        r.y = w0*a.z + w1*a.w + w2*b.x + w3*b.y + w4*b.z + w5*b.w + w6*c.x;
        r.z = w0*a.w + w1*b.x + w2*b.y + w3*b.z + w4*b.w + w5*c.x + w6*c.y;
        r.w = w0*b.x + w1*b.y + w2*b.z + w3*b.w + w4*c.x + w5*c.y + w6*c.z;
        *reinterpret_cast<float4*>(out + base + q) = r;
    }
}

extern "C" void kernel_launch(void* const* d_in, const int* in_sizes, int n_in,
                              void* d_out, int out_size) {
    const float* x = (const float*)d_in[0];
    const float* w = (const float*)d_in[1];
    float* out = (float*)d_out;

    const int rows = in_sizes[0] / T_LEN;   // B*C = 16384

    lconv1d_cpasync_kernel<<<rows, THREADS>>>(x, w, out);
}

// round 8
// speedup vs baseline: 1.0458x; 1.0458x over previous
#include <cuda_runtime.h>
#include <cstdint>

// Depthwise conv1d, K=7, 'same' padding, softmax over taps — single fused kernel.
// x: (B, C, T) fp32; weight: (H, 1, 7); head for channel c is c % H (H=16).
// R2 tile chassis (best measured DRAM%): TILE=2048, 8KB smem, MLP=2,
// register-reused middle chunk. Softmax fused with __expf (MUFU) so warp 0's
// prologue chain (~400cyc) hides fully under the ~600cyc tile DRAM loads.

#define KSIZE 7
#define TILE 2048
#define HALF (TILE / 2)
#define THREADS 256
#define SHIFT 4   // s[SHIFT + i] = x[t0 + i]; halo lives at s[1..3]
#define T_LEN 4096

__global__ __launch_bounds__(THREADS)
void lconv1d_fused_kernel(const float* __restrict__ x,
                          const float* __restrict__ wraw,
                          float* __restrict__ out) {
    __shared__ float s[SHIFT + TILE + 3];
    __shared__ float sw[KSIZE];

    const int row = blockIdx.y;               // b*C + c
    const int t0  = blockIdx.x * TILE;
    const size_t base = (size_t)row * T_LEN + t0;
    const int tid = threadIdx.x;
    const int p0 = tid * 4;
    const int p1 = p0 + HALF;

    // Two independent main-tile loads per thread (MLP=2), aligned STS.128.
    const float4 v0 = *reinterpret_cast<const float4*>(x + base + p0);
    const float4 v1 = *reinterpret_cast<const float4*>(x + base + p1);
    *reinterpret_cast<float4*>(&s[SHIFT + p0]) = v0;
    *reinterpret_cast<float4*>(&s[SHIFT + p1]) = v1;

    // Halos (3 left, 3 right) with zero padding at row boundaries.
    if (tid < 3) {
        s[1 + tid]            = (t0 > 0)            ? x[base - 3 + tid]    : 0.f;
        s[SHIFT + TILE + tid] = (t0 + TILE < T_LEN) ? x[base + TILE + tid] : 0.f;
    }

    // Fused softmax over this row's head taps (threads 0..6).
    // __expf = MUFU EX2 path: whole chain ~400cyc, hidden under tile DRAM loads.
    if (tid < KSIZE) {
        const int h = row & 15;               // C=1024 multiple of H=16
        float v[KSIZE];
        float m = -1e30f;
        #pragma unroll
        for (int k = 0; k < KSIZE; k++) {
            v[k] = __ldg(&wraw[h * KSIZE + k]);
            m = fmaxf(m, v[k]);
        }
        float sum = 0.f;
        #pragma unroll
        for (int k = 0; k < KSIZE; k++) sum += __expf(v[k] - m);
        sw[tid] = __expf(v[tid] - m) / sum;
    }

    __syncthreads();

    const float w0 = sw[0], w1 = sw[1], w2 = sw[2], w3 = sw[3],
                w4 = sw[4], w5 = sw[5], w6 = sw[6];

    // Chunk 0: outputs [p0 .. p0+3]. Middle float4 == v0 (register reuse).
    {
        const float4 a = *reinterpret_cast<const float4*>(&s[p0]);
        const float4 b = v0;
        const float4 c = *reinterpret_cast<const float4*>(&s[p0 + 8]);
        float4 r;
        r.x = w0*a.y + w1*a.z + w2*a.w + w3*b.x + w4*b.y + w5*b.z + w6*b.w;
        r.y = w0*a.z + w1*a.w + w2*b.x + w3*b.y + w4*b.z + w5*b.w + w6*c.x;
        r.z = w0*a.w + w1*b.x + w2*b.y + w3*b.z + w4*b.w + w5*c.x + w6*c.y;
        r.w = w0*b.x + w1*b.y + w2*b.z + w3*b.w + w4*c.x + w5*c.y + w6*c.z;
        *reinterpret_cast<float4*>(out + base + p0) = r;
    }

    // Chunk 1: outputs [p1 .. p1+3]. Middle float4 == v1.
    {
        const float4 a = *reinterpret_cast<const float4*>(&s[p1]);
        const float4 b = v1;
        const float4 c = *reinterpret_cast<const float4*>(&s[p1 + 8]);
        float4 r;
        r.x = w0*a.y + w1*a.z + w2*a.w + w3*b.x + w4*b.y + w5*b.z + w6*b.w;
        r.y = w0*a.z + w1*a.w + w2*b.x + w3*b.y + w4*b.z + w5*b.w + w6*c.x;
        r.z = w0*a.w + w1*b.x + w2*b.y + w3*b.z + w4*b.w + w5*c.x + w6*c.y;
        r.w = w0*b.x + w1*b.y + w2*b.z + w3*b.w + w4*c.x + w5*c.y + w6*c.z;
        *reinterpret_cast<float4*>(out + base + p1) = r;
    }
}

extern "C" void kernel_launch(void* const* d_in, const int* in_sizes, int n_in,
                              void* d_out, int out_size) {
    const float* x = (const float*)d_in[0];
    const float* w = (const float*)d_in[1];
    float* out = (float*)d_out;

    const int rows = in_sizes[0] / T_LEN;   // B*C = 16384

    dim3 grid(T_LEN / TILE, rows);          // (2, 16384)
    lconv1d_fused_kernel<<<grid, THREADS>>>(x, w, out);
}